// round 14
// baseline (speedup 1.0000x reference)
#include <cuda_runtime.h>
#include <math.h>
#include <stdint.h>

// ---------------------------------------------------------------------------
// SwinTransformerFusion: B=8, DIM=192, C2=384, H=W=60, pad->63x63, WS=7,
// SHIFT=3, HEADS=4, HD=96, NW=81 win/img, N=49 tok/win.
// ---------------------------------------------------------------------------
constexpr int kTok  = 8 * 63 * 63;   // 31752 (== 648 windows * 49 tokens)
constexpr int kC2   = 384;
constexpr int kMlp  = 1536;
constexpr int kDim  = 192;

__device__ float g_Z   [kTok * kC2];
__device__ float g_Wtok[kTok * kC2];
__device__ float g_QKV [(size_t)kTok * 3 * kC2];
__device__ float g_Aout[kTok * kC2];
__device__ float g_Z2  [kTok * kC2];
__device__ float g_H   [(size_t)kTok * kMlp];
__device__ float g_Zf  [kTok * kC2];
__device__ float g_W2  [kDim * kC2 * 9];
__device__ float g_W1p [kMlp * kC2];     // fc1_w * n2_w
__device__ float g_Hn  [kMlp];           // row sums of W1p
__device__ float g_Cn  [kMlp];           // n2_b @ fc1_w^T + fc1_b
__device__ float g_Stat[kTok * 2];       // (mu, rs) per row of Z2

// ---------------------------------------------------------------------------
__device__ __forceinline__ float2 reduce2_128(float a, float b, float2* sh) {
    #pragma unroll
    for (int o = 16; o; o >>= 1) {
        a += __shfl_down_sync(0xffffffffu, a, o);
        b += __shfl_down_sync(0xffffffffu, b, o);
    }
    int tid = threadIdx.x;
    if ((tid & 31) == 0) sh[tid >> 5] = make_float2(a, b);
    __syncthreads();
    float2 r = sh[0];
    r.x += sh[1].x + sh[2].x + sh[3].x;
    r.y += sh[1].y + sh[2].y + sh[3].y;
    __syncthreads();
    return r;
}

// ---------------------------------------------------------------------------
__global__ void prep_kernel(const float* __restrict__ x, const float* __restrict__ g,
                            const float* __restrict__ nw, const float* __restrict__ nb,
                            const float* __restrict__ n1w, const float* __restrict__ n1b)
{
    __shared__ float2 sh[4];
    int pos = blockIdx.x;
    int b = pos / 3969, rc = pos - b * 3969;
    int r = rc / 63, c = rc - (rc / 63) * 63;
    int tid = threadIdx.x;
    bool inside = (r < 60) && (c < 60);
    float v[3];
    #pragma unroll
    for (int q = 0; q < 3; ++q) {
        int ch = q * 128 + tid;
        float t = 0.f;
        if (inside) {
            const float* src = (ch < 192) ? x : g;
            int cc = (ch < 192) ? ch : ch - 192;
            t = src[(((size_t)b * 192 + cc) * 60 + r) * 60 + c];
        }
        v[q] = t;
    }
    float s = v[0] + v[1] + v[2];
    float s2 = v[0]*v[0] + v[1]*v[1] + v[2]*v[2];
    float2 t1 = reduce2_128(s, s2, sh);
    float mu  = t1.x * (1.f / 384.f);
    float var = t1.y * (1.f / 384.f) - mu * mu;
    float rs  = rsqrtf(var + 1e-5f);

    float z[3];
    s = 0.f; s2 = 0.f;
    #pragma unroll
    for (int q = 0; q < 3; ++q) {
        int ch = q * 128 + tid;
        float zz = (v[q] - mu) * rs * nw[ch] + nb[ch];
        z[q] = zz;
        g_Z[(size_t)pos * 384 + ch] = zz;
        s += zz; s2 += zz * zz;
    }
    float2 t2 = reduce2_128(s, s2, sh);
    float mu2  = t2.x * (1.f / 384.f);
    float var2 = t2.y * (1.f / 384.f) - mu2 * mu2;
    float rs2  = rsqrtf(var2 + 1e-5f);

    int rr = r + 60; if (rr >= 63) rr -= 63;
    int cc = c + 60; if (cc >= 63) cc -= 63;
    int widx = (rr / 7) * 9 + cc / 7;
    int tok  = (rr % 7) * 7 + cc % 7;
    size_t wo = ((size_t)(b * 81 + widx) * 49 + tok) * 384;
    #pragma unroll
    for (int q = 0; q < 3; ++q) {
        int ch = q * 128 + tid;
        g_Wtok[wo + ch] = (z[q] - mu2) * rs2 * n1w[ch] + n1b[ch];
    }
}

// ---------------------------------------------------------------------------
// per-row LN stats only (mu, rs) for the fused LN->fc1 GEMM
// ---------------------------------------------------------------------------
__global__ void ln_stats(const float* __restrict__ in)
{
    __shared__ float2 sh[4];
    int pos = blockIdx.x, tid = threadIdx.x;
    float v[3];
    #pragma unroll
    for (int q = 0; q < 3; ++q) v[q] = in[(size_t)pos * 384 + q * 128 + tid];
    float s = v[0] + v[1] + v[2];
    float s2 = v[0]*v[0] + v[1]*v[1] + v[2]*v[2];
    float2 t = reduce2_128(s, s2, sh);
    float mu  = t.x * (1.f / 384.f);
    float var = t.y * (1.f / 384.f) - mu * mu;
    if (tid == 0) {
        g_Stat[2 * pos]     = mu;
        g_Stat[2 * pos + 1] = rsqrtf(var + 1e-5f);
    }
}

// ---------------------------------------------------------------------------
// fold n2 LN into fc1 weights: W1p = fc1_w * n2_w (per col), h = row sums,
// c = n2_b @ fc1_w^T + fc1_b
// ---------------------------------------------------------------------------
__global__ void prep_fc1(const float* __restrict__ fc1_w, const float* __restrict__ fc1_b,
                         const float* __restrict__ n2w, const float* __restrict__ n2b)
{
    __shared__ float2 sh[4];
    int n = blockIdx.x, tid = threadIdx.x;
    float hs = 0.f, cs = 0.f;
    #pragma unroll
    for (int q = 0; q < 3; ++q) {
        int k = q * 128 + tid;
        float w = fc1_w[(size_t)n * 384 + k];
        float wp = w * n2w[k];
        g_W1p[(size_t)n * 384 + k] = wp;
        hs += wp;
        cs += w * n2b[k];
    }
    float2 t = reduce2_128(hs, cs, sh);
    if (tid == 0) { g_Hn[n] = t.x; g_Cn[n] = t.y + fc1_b[n]; }
}

// ---------------------------------------------------------------------------
__global__ void repack_conv(const float* __restrict__ w)
{
    int i = blockIdx.x * 256 + threadIdx.x;
    if (i >= kDim * kC2 * 9) return;
    int o = i / 3456, k = i - o * 3456;
    int tap = k / 384, ci = k - tap * 384;
    g_W2[i] = w[((size_t)o * 384 + ci) * 9 + tap];
}

// ---------------------------------------------------------------------------
__device__ __forceinline__ void mma_tf32(float* c, const uint32_t* a, const uint32_t* b) {
    asm volatile("mma.sync.aligned.m16n8k8.row.col.f32.tf32.tf32.f32 "
        "{%0,%1,%2,%3}, {%4,%5,%6,%7}, {%8,%9}, {%0,%1,%2,%3};"
        : "+f"(c[0]), "+f"(c[1]), "+f"(c[2]), "+f"(c[3])
        : "r"(a[0]), "r"(a[1]), "r"(a[2]), "r"(a[3]), "r"(b[0]), "r"(b[1]));
}
__device__ __forceinline__ void ldsm_x4(uint32_t* d, uint32_t addr) {
    asm volatile("ldmatrix.sync.aligned.m8n8.x4.shared.b16 {%0,%1,%2,%3}, [%4];"
        : "=r"(d[0]), "=r"(d[1]), "=r"(d[2]), "=r"(d[3]) : "r"(addr));
}

// ---------------------------------------------------------------------------
// Tensor-core attention (one block per (window, head), 4 warps).
// ---------------------------------------------------------------------------
__global__ __launch_bounds__(128, 4)
void attn_mma(const float* __restrict__ rpb)
{
    __shared__ __align__(16) float KsP[56 * 100];   // phase1 K, phase2 P
    __shared__ __align__(16) float Vt[96 * 61];     // V^T [d][j], stride 61
    const int blk = blockIdx.x;
    const int win = blk >> 2, h = blk & 3;
    const int widx = win % 81;
    const int wr = widx / 9, wc = widx % 9;
    const int tid = threadIdx.x;
    const int warp = tid >> 5, lane = tid & 31;
    const int lq = lane >> 2, lr4 = lane & 3;
    const int wm = warp * 16;
    const size_t base = (size_t)win * 49 * 1152 + h * 96;

    for (int e = tid; e < 7 * 100; e += 128)
        KsP[(49 + e / 100) * 100 + (e - (e / 100) * 100)] = 0.f;
    for (int e = tid; e < 96 * 7; e += 128)
        Vt[(e / 7) * 61 + 49 + (e - (e / 7) * 7)] = 0.f;
    for (int e = tid; e < 49 * 24; e += 128) {
        int i = e / 24, dq = e - i * 24;
        *(float4*)&KsP[i * 100 + dq * 4] =
            *(const float4*)(g_QKV + base + 384 + (size_t)i * 1152 + dq * 4);
    }
    for (int e = tid; e < 49 * 96; e += 128) {
        int j = e / 96, d = e - j * 96;
        Vt[d * 61 + j] = g_QKV[base + 768 + (size_t)j * 1152 + d];
    }

    uint32_t qf[12][4];
    {
        int r0 = wm + lq;      if (r0 > 48) r0 = 48;
        int r1 = wm + lq + 8;  if (r1 > 48) r1 = 48;
        const float* Q0 = g_QKV + base + (size_t)r0 * 1152;
        const float* Q1 = g_QKV + base + (size_t)r1 * 1152;
        #pragma unroll
        for (int kt = 0; kt < 12; ++kt) {
            int c0 = kt * 8 + lr4;
            qf[kt][0] = __float_as_uint(Q0[c0]);
            qf[kt][1] = __float_as_uint(Q1[c0]);
            qf[kt][2] = __float_as_uint(Q0[c0 + 4]);
            qf[kt][3] = __float_as_uint(Q1[c0 + 4]);
        }
    }
    __syncthreads();

    float acc[7][4];
    #pragma unroll
    for (int nt = 0; nt < 7; ++nt)
        #pragma unroll
        for (int c = 0; c < 4; ++c) acc[nt][c] = 0.f;
    #pragma unroll
    for (int kt = 0; kt < 12; ++kt) {
        #pragma unroll
        for (int nt = 0; nt < 7; ++nt) {
            uint32_t bf[2];
            int nrow = nt * 8 + lq;
            bf[0] = __float_as_uint(KsP[nrow * 100 + kt * 8 + lr4]);
            bf[1] = __float_as_uint(KsP[nrow * 100 + kt * 8 + lr4 + 4]);
            mma_tf32(acc[nt], qf[kt], bf);
        }
    }
    __syncthreads();

    const float scale = 0.10206207261596577f;
    #pragma unroll
    for (int h2 = 0; h2 < 2; ++h2) {
        int i = wm + lq + 8 * h2;
        bool rvalid = i < 49;
        int yi = i / 7, xi = i - yi * 7;
        int gyi = wr * 7 + yi, gxi = wc * 7 + xi;
        int li = ((gyi < 56) ? 0 : ((gyi < 60) ? 1 : 2)) * 3 +
                 ((gxi < 56) ? 0 : ((gxi < 60) ? 1 : 2));
        float pv[14];
        float m = -1e30f;
        #pragma unroll
        for (int nt = 0; nt < 7; ++nt)
            #pragma unroll
            for (int c = 0; c < 2; ++c) {
                int j = nt * 8 + 2 * lr4 + c;
                float v;
                if (j < 49 && rvalid) {
                    int yj = j / 7, xj = j - yj * 7;
                    float bias = rpb[((yi - yj + 6) * 13 + (xi - xj + 6)) * 4 + h];
                    int gyj = wr * 7 + yj, gxj = wc * 7 + xj;
                    int lj = ((gyj < 56) ? 0 : ((gyj < 60) ? 1 : 2)) * 3 +
                             ((gxj < 56) ? 0 : ((gxj < 60) ? 1 : 2));
                    v = acc[nt][h2 * 2 + c] * scale + bias + ((li != lj) ? -100.f : 0.f);
                } else {
                    v = (j < 49) ? 0.f : -1e30f;
                }
                pv[nt * 2 + c] = v;
                m = fmaxf(m, v);
            }
        m = fmaxf(m, __shfl_xor_sync(0xffffffffu, m, 1));
        m = fmaxf(m, __shfl_xor_sync(0xffffffffu, m, 2));
        float s = 0.f;
        #pragma unroll
        for (int t = 0; t < 14; ++t) {
            float e = (pv[t] > -1e29f) ? __expf(pv[t] - m) : 0.f;
            pv[t] = e; s += e;
        }
        s += __shfl_xor_sync(0xffffffffu, s, 1);
        s += __shfl_xor_sync(0xffffffffu, s, 2);
        float inv = 1.f / s;
        #pragma unroll
        for (int nt = 0; nt < 7; ++nt)
            #pragma unroll
            for (int c = 0; c < 2; ++c)
                KsP[i * 60 + nt * 8 + 2 * lr4 + c] = pv[nt * 2 + c] * inv;
    }
    __syncthreads();

    float oacc[12][4];
    #pragma unroll
    for (int dt = 0; dt < 12; ++dt)
        #pragma unroll
        for (int c = 0; c < 4; ++c) oacc[dt][c] = 0.f;
    #pragma unroll
    for (int kt = 0; kt < 7; ++kt) {
        uint32_t af[4];
        int r0 = wm + lq, c0 = kt * 8 + lr4;
        af[0] = __float_as_uint(KsP[r0 * 60 + c0]);
        af[1] = __float_as_uint(KsP[(r0 + 8) * 60 + c0]);
        af[2] = __float_as_uint(KsP[r0 * 60 + c0 + 4]);
        af[3] = __float_as_uint(KsP[(r0 + 8) * 60 + c0 + 4]);
        #pragma unroll
        for (int dt = 0; dt < 12; ++dt) {
            uint32_t bf[2];
            int drow = dt * 8 + lq;
            bf[0] = __float_as_uint(Vt[drow * 61 + c0]);
            bf[1] = __float_as_uint(Vt[drow * 61 + c0 + 4]);
            mma_tf32(oacc[dt], af, bf);
        }
    }

    #pragma unroll
    for (int h2 = 0; h2 < 2; ++h2) {
        int i = wm + lq + 8 * h2;
        if (i >= 49) continue;
        size_t ro = ((size_t)win * 49 + i) * 384 + h * 96;
        #pragma unroll
        for (int dt = 0; dt < 12; ++dt) {
            int d = dt * 8 + 2 * lr4;
            *(float2*)&g_Aout[ro + d] =
                make_float2(oacc[dt][h2 * 2], oacc[dt][h2 * 2 + 1]);
        }
    }
}

// ---------------------------------------------------------------------------
// cp.async helpers
// ---------------------------------------------------------------------------
__device__ __forceinline__ void cpasync16(void* dst, const void* src, bool pred) {
    uint32_t d = (uint32_t)__cvta_generic_to_shared(dst);
    int sz = pred ? 16 : 0;
    asm volatile("cp.async.cg.shared.global [%0], [%1], 16, %2;"
                 :: "r"(d), "l"(src), "r"(sz));
}
__device__ __forceinline__ void cp_commit() {
    asm volatile("cp.async.commit_group;");
}
template<int NN>
__device__ __forceinline__ void cp_wait() {
    asm volatile("cp.async.wait_group %0;" :: "n"(NN));
}

// ---------------------------------------------------------------------------
// TF32 GEMM, BK=32, 3-stage cp.async (wait<=1: two COMPUTE spans of cover),
// HALF the barriers of BK=16. Fragments via ldmatrix.x4. 128x128 tile,
// 256 threads, warp tile 32x64, smem stride 36 (==4 mod 32: LDSM phases
// cover all 32 banks; 144B rows keep 16B cp.async alignment).
// MODE: 0 plain, 2 +extra, 3 window-reverse scatter (+shortcut),
//       4 implicit-GEMM conv gather + NCHW store + x residual,
//       5 fused LN->fc1->gelu: v = gelu(rs*(acc - mu*bias[n]) + extra[n])
// ---------------------------------------------------------------------------
constexpr int GST   = 3;                          // pipeline stages
constexpr int GSTW  = 128 * 36;                   // words per stage per operand
constexpr int GSTG  = GSTW * 4;                   // bytes per stage per operand
constexpr int GSMEM = GST * 2 * GSTG;             // 110592 bytes

template<int MODE>
__global__ __launch_bounds__(256, 2)
void gemm_tc(const float* __restrict__ A, const float* __restrict__ W,
             const float* __restrict__ bias, float* __restrict__ C,
             const float* __restrict__ extra, int M, int N, int K,
             const float* __restrict__ stats)
{
    constexpr int ST = GST;
    extern __shared__ __align__(16) uint32_t dyn[];
    uint32_t* As = dyn;                       // ST stages of 128*36
    uint32_t* Bs = dyn + ST * GSTW;           // ST stages of 128*36
    const uint32_t smem0 = (uint32_t)__cvta_generic_to_shared(dyn);

    const int tid  = threadIdx.x;
    const int lane = tid & 31, warp = tid >> 5;
    const int wm = (warp >> 1) * 32, wn = (warp & 1) * 64;
    const int m0 = blockIdx.y << 7, n0 = blockIdx.x << 7;
    const int lr  = tid >> 1;             // loader row 0..127
    const int lcb = (tid & 1) * 16;       // loader col base: 0 or 16

    // per-thread ldmatrix byte offsets (within one operand stage)
    uint32_t aoff[2], boff[4];
    #pragma unroll
    for (int mt = 0; mt < 2; ++mt)
        aoff[mt] = (uint32_t)(((wm + mt * 16 + (lane & 15)) * 36 +
                               ((lane >> 4) << 2)) * 4);
    #pragma unroll
    for (int p = 0; p < 4; ++p)
        boff[p] = (uint32_t)(((wn + p * 16 + ((lane >> 4) << 3) + (lane & 7)) * 36 +
                              (((lane >> 3) & 1) << 2)) * 4);

    float acc[2][8][4];
    #pragma unroll
    for (int a = 0; a < 2; ++a)
        #pragma unroll
        for (int b = 0; b < 8; ++b)
            #pragma unroll
            for (int c = 0; c < 4; ++c) acc[a][b][c] = 0.f;

    int cb = 0, crr = 0, ccc = 0;
    if (MODE == 4) {
        int m = m0 + lr; if (m >= M) m = 0;
        cb = m / 3600; int pix = m - cb * 3600;
        crr = pix / 60; ccc = pix - crr * 60;
    }

    const int KT = K >> 5;

    auto LOADA = [&](int kt, int buf) {
        int k0 = kt * 32;
        uint32_t* as = As + buf * GSTW;
        uint32_t* bs = Bs + buf * GSTW;
        int m = m0 + lr;
        int n = n0 + lr;
        #pragma unroll
        for (int j = 0; j < 4; ++j) {
            int col = lcb + 4 * j;
            int k = k0 + col;
            const float* asrc = A;
            bool ap = false;
            if (MODE == 4) {
                int tap = k / 384, ci = k - tap * 384;
                int rr = crr + tap / 3 - 1, cc = ccc + (tap % 3) - 1;
                ap = (m < M) && (rr >= 0) && (rr < 60) && (cc >= 0) && (cc < 60);
                if (ap) asrc = A + ((size_t)(cb * 63 + rr) * 63 + cc) * 384 + ci;
            } else {
                ap = (m < M);
                if (ap) asrc = A + (size_t)m * K + k;
            }
            cpasync16(&as[lr * 36 + col], asrc, ap);
            const float* bsrc = (n < N) ? (W + (size_t)n * K + k) : W;
            cpasync16(&bs[lr * 36 + col], bsrc, n < N);
        }
    };

    auto COMPUTE = [&](int buf) {
        const uint32_t abase = smem0 + buf * GSTG;
        const uint32_t bbase = smem0 + (ST + buf) * GSTG;
        #pragma unroll
        for (int ks = 0; ks < 32; ks += 8) {
            uint32_t af[2][4], bf[8][2];
            #pragma unroll
            for (int mt = 0; mt < 2; ++mt)
                ldsm_x4(af[mt], abase + aoff[mt] + ks * 4);
            #pragma unroll
            for (int p = 0; p < 4; ++p) {
                uint32_t d[4];
                ldsm_x4(d, bbase + boff[p] + ks * 4);
                bf[2 * p][0]     = d[0];
                bf[2 * p][1]     = d[1];
                bf[2 * p + 1][0] = d[2];
                bf[2 * p + 1][1] = d[3];
            }
            #pragma unroll
            for (int mt = 0; mt < 2; ++mt)
                #pragma unroll
                for (int nt = 0; nt < 8; ++nt)
                    mma_tf32(acc[mt][nt], af[mt], bf[nt]);
        }
    };

    #pragma unroll
    for (int s = 0; s < ST - 1; ++s) {
        if (s < KT) LOADA(s, s);
        cp_commit();
    }
    for (int kt = 0; kt < KT; ++kt) {
        cp_wait<ST - 2>();
        __syncthreads();
        COMPUTE(kt % ST);
        int nx = kt + ST - 1;
        if (nx < KT) LOADA(nx, nx % ST);
        cp_commit();
    }

    // ---- epilogue ----
    #pragma unroll
    for (int mt = 0; mt < 2; ++mt) {
        #pragma unroll
        for (int half = 0; half < 2; ++half) {
            int m = m0 + wm + mt * 16 + (lane >> 2) + half * 8;
            if (m >= M) continue;
            size_t rowoff = 0;
            if (MODE == 0 || MODE == 2 || MODE == 5) {
                rowoff = (size_t)m * N;
            } else if (MODE == 3) {
                int b = m / 3969;
                int rem = m - b * 3969;
                int widx = rem / 49, tok = rem - widx * 49;
                int rr = (widx / 9) * 7 + tok / 7;
                int cc = (widx % 9) * 7 + tok % 7;
                int r2 = rr + 3; if (r2 >= 63) r2 -= 63;
                int c2 = cc + 3; if (c2 >= 63) c2 -= 63;
                rowoff = (size_t)((b * 63 + r2) * 63 + c2) * 384;
            }
            int ob = 0, orr = 0, occ = 0;
            if (MODE == 4) {
                ob = m / 3600; int pix = m - ob * 3600;
                orr = pix / 60; occ = pix - orr * 60;
            }
            float mu = 0.f, rs = 0.f;
            if (MODE == 5) { mu = stats[2 * m]; rs = stats[2 * m + 1]; }
            #pragma unroll
            for (int nt = 0; nt < 8; ++nt) {
                int n = n0 + wn + nt * 8 + 2 * (lane & 3);
                if (n >= N) continue;
                if (MODE == 5) {
                    float v0 = rs * (acc[mt][nt][half * 2]     - mu * bias[n])     + extra[n];
                    float v1 = rs * (acc[mt][nt][half * 2 + 1] - mu * bias[n + 1]) + extra[n + 1];
                    v0 = 0.5f * v0 * (1.f + erff(v0 * 0.70710678118654752f));
                    v1 = 0.5f * v1 * (1.f + erff(v1 * 0.70710678118654752f));
                    *(float2*)&C[rowoff + n] = make_float2(v0, v1);
                    continue;
                }
                float v0 = acc[mt][nt][half * 2]     + bias[n];
                float v1 = acc[mt][nt][half * 2 + 1] + bias[n + 1];
                if (MODE == 0) {
                    *(float2*)&C[rowoff + n] = make_float2(v0, v1);
                } else if (MODE == 2 || MODE == 3) {
                    float2 e = *(const float2*)&extra[rowoff + n];
                    *(float2*)&C[rowoff + n] = make_float2(v0 + e.x, v1 + e.y);
                } else {
                    #pragma unroll
                    for (int c = 0; c < 2; ++c) {
                        int nn = n + c;
                        if (nn >= N) continue;
                        float v = (c == 0) ? v0 : v1;
                        size_t o = (((size_t)ob * 192 + nn) * 60 + orr) * 60 + occ;
                        C[o] = v + extra[o];
                    }
                }
            }
        }
    }
}

// ---------------------------------------------------------------------------
extern "C" void kernel_launch(void* const* d_in, const int* in_sizes, int n_in,
                              void* d_out, int out_size)
{
    const float* x      = (const float*)d_in[0];
    const float* g      = (const float*)d_in[1];
    const float* norm_w = (const float*)d_in[2];
    const float* norm_b = (const float*)d_in[3];
    const float* n1_w   = (const float*)d_in[4];
    const float* n1_b   = (const float*)d_in[5];
    const float* qkv_w  = (const float*)d_in[6];
    const float* qkv_b  = (const float*)d_in[7];
    const float* proj_w = (const float*)d_in[8];
    const float* proj_b = (const float*)d_in[9];
    const float* rpb    = (const float*)d_in[10];
    const float* n2_w   = (const float*)d_in[11];
    const float* n2_b   = (const float*)d_in[12];
    const float* fc1_w  = (const float*)d_in[13];
    const float* fc1_b  = (const float*)d_in[14];
    const float* fc2_w  = (const float*)d_in[15];
    const float* fc2_b  = (const float*)d_in[16];
    const float* conv_w = (const float*)d_in[17];
    const float* conv_b = (const float*)d_in[18];
    float* out = (float*)d_out;

    float *pZ, *pWtok, *pQKV, *pAout, *pZ2, *pH, *pZf, *pW2;
    float *pW1p, *pHn, *pCn, *pStat;
    cudaGetSymbolAddress((void**)&pZ,    g_Z);
    cudaGetSymbolAddress((void**)&pWtok, g_Wtok);
    cudaGetSymbolAddress((void**)&pQKV,  g_QKV);
    cudaGetSymbolAddress((void**)&pAout, g_Aout);
    cudaGetSymbolAddress((void**)&pZ2,   g_Z2);
    cudaGetSymbolAddress((void**)&pH,    g_H);
    cudaGetSymbolAddress((void**)&pZf,   g_Zf);
    cudaGetSymbolAddress((void**)&pW2,   g_W2);
    cudaGetSymbolAddress((void**)&pW1p,  g_W1p);
    cudaGetSymbolAddress((void**)&pHn,   g_Hn);
    cudaGetSymbolAddress((void**)&pCn,   g_Cn);
    cudaGetSymbolAddress((void**)&pStat, g_Stat);

    cudaFuncSetAttribute(gemm_tc<0>, cudaFuncAttributeMaxDynamicSharedMemorySize, GSMEM);
    cudaFuncSetAttribute(gemm_tc<2>, cudaFuncAttributeMaxDynamicSharedMemorySize, GSMEM);
    cudaFuncSetAttribute(gemm_tc<3>, cudaFuncAttributeMaxDynamicSharedMemorySize, GSMEM);
    cudaFuncSetAttribute(gemm_tc<4>, cudaFuncAttributeMaxDynamicSharedMemorySize, GSMEM);
    cudaFuncSetAttribute(gemm_tc<5>, cudaFuncAttributeMaxDynamicSharedMemorySize, GSMEM);

    const int MT = (kTok + 127) / 128;  // 249

    repack_conv<<<(kDim * kC2 * 9 + 255) / 256, 256>>>(conv_w);
    prep_fc1<<<kMlp, 128>>>(fc1_w, fc1_b, n2_w, n2_b);
    prep_kernel<<<kTok, 128>>>(x, g, norm_w, norm_b, n1_w, n1_b);
    gemm_tc<0><<<dim3(9, MT), 256, GSMEM>>>(pWtok, qkv_w, qkv_b, pQKV, nullptr, kTok, 1152, 384, nullptr);
    attn_mma<<<648 * 4, 128>>>(rpb);
    gemm_tc<3><<<dim3(3, MT), 256, GSMEM>>>(pAout, proj_w, proj_b, pZ2, pZ, kTok, 384, 384, nullptr);
    ln_stats<<<kTok, 128>>>(pZ2);
    gemm_tc<5><<<dim3(12, MT), 256, GSMEM>>>(pZ2, pW1p, pHn, pH, pCn, kTok, 1536, 384, pStat);
    gemm_tc<2><<<dim3(3, MT), 256, GSMEM>>>(pH, fc2_w, fc2_b, pZf, pZ2, kTok, 384, 1536, nullptr);
    gemm_tc<4><<<dim3(2, 225), 256, GSMEM>>>(pZf, pW2, conv_b, out, x, 28800, 192, 3456, nullptr);
}

// round 15
// speedup vs baseline: 1.2870x; 1.2870x over previous
#include <cuda_runtime.h>
#include <math.h>
#include <stdint.h>

// ---------------------------------------------------------------------------
// SwinTransformerFusion: B=8, DIM=192, C2=384, H=W=60, pad->63x63, WS=7,
// SHIFT=3, HEADS=4, HD=96, NW=81 win/img, N=49 tok/win.
// ---------------------------------------------------------------------------
constexpr int kTok  = 8 * 63 * 63;   // 31752 (== 648 windows * 49 tokens)
constexpr int kC2   = 384;
constexpr int kMlp  = 1536;
constexpr int kDim  = 192;

__device__ float g_Z   [kTok * kC2];
__device__ float g_Wtok[kTok * kC2];
__device__ float g_QKV [(size_t)kTok * 3 * kC2];
__device__ float g_Aout[kTok * kC2];
__device__ float g_Z2  [kTok * kC2];
__device__ float g_H   [(size_t)kTok * kMlp];
__device__ float g_Zf  [kTok * kC2];
__device__ float g_W2  [kDim * kC2 * 9];
__device__ float g_W1p [kMlp * kC2];     // fc1_w * n2_w
__device__ float g_Hn  [kMlp];           // row sums of W1p
__device__ float g_Cn  [kMlp];           // n2_b @ fc1_w^T + fc1_b
__device__ float g_Stat[kTok * 2];       // (mu, rs) per row of Z2

// ---------------------------------------------------------------------------
__device__ __forceinline__ float2 reduce2_128(float a, float b, float2* sh) {
    #pragma unroll
    for (int o = 16; o; o >>= 1) {
        a += __shfl_down_sync(0xffffffffu, a, o);
        b += __shfl_down_sync(0xffffffffu, b, o);
    }
    int tid = threadIdx.x;
    if ((tid & 31) == 0) sh[tid >> 5] = make_float2(a, b);
    __syncthreads();
    float2 r = sh[0];
    r.x += sh[1].x + sh[2].x + sh[3].x;
    r.y += sh[1].y + sh[2].y + sh[3].y;
    __syncthreads();
    return r;
}

// ---------------------------------------------------------------------------
// prep: warp-per-position (no barriers). concat+pad -> LN(norm) -> z ;
// LN(n1) -> roll(-3,-3)+window partition.
// ---------------------------------------------------------------------------
__global__ __launch_bounds__(128)
void prep_kernel(const float* __restrict__ x, const float* __restrict__ g,
                 const float* __restrict__ nw, const float* __restrict__ nb,
                 const float* __restrict__ n1w, const float* __restrict__ n1b)
{
    int pos  = blockIdx.x * 4 + (threadIdx.x >> 5);
    int lane = threadIdx.x & 31;
    int b = pos / 3969, rc = pos - b * 3969;
    int r = rc / 63, c = rc - (rc / 63) * 63;
    bool inside = (r < 60) && (c < 60);

    float v[12];
    float s = 0.f, s2 = 0.f;
    #pragma unroll
    for (int q = 0; q < 12; ++q) {
        int ch = q * 32 + lane;
        float t = 0.f;
        if (inside) {
            const float* src = (q < 6) ? x : g;
            int cc = (q < 6) ? ch : ch - 192;
            t = src[(((size_t)b * 192 + cc) * 60 + r) * 60 + c];
        }
        v[q] = t; s += t; s2 += t * t;
    }
    #pragma unroll
    for (int o = 16; o; o >>= 1) {
        s  += __shfl_xor_sync(0xffffffffu, s, o);
        s2 += __shfl_xor_sync(0xffffffffu, s2, o);
    }
    float mu  = s * (1.f / 384.f);
    float var = s2 * (1.f / 384.f) - mu * mu;
    float rs  = rsqrtf(var + 1e-5f);

    float z[12];
    s = 0.f; s2 = 0.f;
    #pragma unroll
    for (int q = 0; q < 12; ++q) {
        int ch = q * 32 + lane;
        float zz = (v[q] - mu) * rs * nw[ch] + nb[ch];
        z[q] = zz;
        g_Z[(size_t)pos * 384 + ch] = zz;
        s += zz; s2 += zz * zz;
    }
    #pragma unroll
    for (int o = 16; o; o >>= 1) {
        s  += __shfl_xor_sync(0xffffffffu, s, o);
        s2 += __shfl_xor_sync(0xffffffffu, s2, o);
    }
    float mu2  = s * (1.f / 384.f);
    float var2 = s2 * (1.f / 384.f) - mu2 * mu2;
    float rs2  = rsqrtf(var2 + 1e-5f);

    int rr = r + 60; if (rr >= 63) rr -= 63;
    int cc = c + 60; if (cc >= 63) cc -= 63;
    int widx = (rr / 7) * 9 + cc / 7;
    int tok  = (rr % 7) * 7 + cc % 7;
    size_t wo = ((size_t)(b * 81 + widx) * 49 + tok) * 384;
    #pragma unroll
    for (int q = 0; q < 12; ++q) {
        int ch = q * 32 + lane;
        g_Wtok[wo + ch] = (z[q] - mu2) * rs2 * n1w[ch] + n1b[ch];
    }
}

// ---------------------------------------------------------------------------
// per-row LN stats (mu, rs): warp-per-row, shfl-only
// ---------------------------------------------------------------------------
__global__ __launch_bounds__(128)
void ln_stats(const float* __restrict__ in)
{
    int pos  = blockIdx.x * 4 + (threadIdx.x >> 5);
    int lane = threadIdx.x & 31;
    float s = 0.f, s2 = 0.f;
    #pragma unroll
    for (int q = 0; q < 12; ++q) {
        float t = in[(size_t)pos * 384 + q * 32 + lane];
        s += t; s2 += t * t;
    }
    #pragma unroll
    for (int o = 16; o; o >>= 1) {
        s  += __shfl_xor_sync(0xffffffffu, s, o);
        s2 += __shfl_xor_sync(0xffffffffu, s2, o);
    }
    if (lane == 0) {
        float mu  = s * (1.f / 384.f);
        float var = s2 * (1.f / 384.f) - mu * mu;
        g_Stat[2 * pos]     = mu;
        g_Stat[2 * pos + 1] = rsqrtf(var + 1e-5f);
    }
}

// ---------------------------------------------------------------------------
// fold n2 LN into fc1 weights
// ---------------------------------------------------------------------------
__global__ void prep_fc1(const float* __restrict__ fc1_w, const float* __restrict__ fc1_b,
                         const float* __restrict__ n2w, const float* __restrict__ n2b)
{
    __shared__ float2 sh[4];
    int n = blockIdx.x, tid = threadIdx.x;
    float hs = 0.f, cs = 0.f;
    #pragma unroll
    for (int q = 0; q < 3; ++q) {
        int k = q * 128 + tid;
        float w = fc1_w[(size_t)n * 384 + k];
        float wp = w * n2w[k];
        g_W1p[(size_t)n * 384 + k] = wp;
        hs += wp;
        cs += w * n2b[k];
    }
    float2 t = reduce2_128(hs, cs, sh);
    if (tid == 0) { g_Hn[n] = t.x; g_Cn[n] = t.y + fc1_b[n]; }
}

// ---------------------------------------------------------------------------
__global__ void repack_conv(const float* __restrict__ w)
{
    int i = blockIdx.x * 256 + threadIdx.x;
    if (i >= kDim * kC2 * 9) return;
    int o = i / 3456, k = i - o * 3456;
    int tap = k / 384, ci = k - tap * 384;
    g_W2[i] = w[((size_t)o * 384 + ci) * 9 + tap];
}

// ---------------------------------------------------------------------------
__device__ __forceinline__ void mma_tf32(float* c, const uint32_t* a, const uint32_t* b) {
    asm volatile("mma.sync.aligned.m16n8k8.row.col.f32.tf32.tf32.f32 "
        "{%0,%1,%2,%3}, {%4,%5,%6,%7}, {%8,%9}, {%0,%1,%2,%3};"
        : "+f"(c[0]), "+f"(c[1]), "+f"(c[2]), "+f"(c[3])
        : "r"(a[0]), "r"(a[1]), "r"(a[2]), "r"(a[3]), "r"(b[0]), "r"(b[1]));
}
__device__ __forceinline__ void ldsm_x4(uint32_t* d, uint32_t addr) {
    asm volatile("ldmatrix.sync.aligned.m8n8.x4.shared.b16 {%0,%1,%2,%3}, [%4];"
        : "=r"(d[0]), "=r"(d[1]), "=r"(d[2]), "=r"(d[3]) : "r"(addr));
}

// ---------------------------------------------------------------------------
// Tensor-core attention (one block per (window, head), 4 warps).
// ---------------------------------------------------------------------------
__global__ __launch_bounds__(128, 4)
void attn_mma(const float* __restrict__ rpb)
{
    __shared__ __align__(16) float KsP[56 * 100];   // phase1 K, phase2 P
    __shared__ __align__(16) float Vt[96 * 61];     // V^T [d][j], stride 61
    const int blk = blockIdx.x;
    const int win = blk >> 2, h = blk & 3;
    const int widx = win % 81;
    const int wr = widx / 9, wc = widx % 9;
    const int tid = threadIdx.x;
    const int warp = tid >> 5, lane = tid & 31;
    const int lq = lane >> 2, lr4 = lane & 3;
    const int wm = warp * 16;
    const size_t base = (size_t)win * 49 * 1152 + h * 96;

    for (int e = tid; e < 7 * 100; e += 128)
        KsP[(49 + e / 100) * 100 + (e - (e / 100) * 100)] = 0.f;
    for (int e = tid; e < 96 * 7; e += 128)
        Vt[(e / 7) * 61 + 49 + (e - (e / 7) * 7)] = 0.f;
    for (int e = tid; e < 49 * 24; e += 128) {
        int i = e / 24, dq = e - i * 24;
        *(float4*)&KsP[i * 100 + dq * 4] =
            *(const float4*)(g_QKV + base + 384 + (size_t)i * 1152 + dq * 4);
    }
    for (int e = tid; e < 49 * 96; e += 128) {
        int j = e / 96, d = e - j * 96;
        Vt[d * 61 + j] = g_QKV[base + 768 + (size_t)j * 1152 + d];
    }

    uint32_t qf[12][4];
    {
        int r0 = wm + lq;      if (r0 > 48) r0 = 48;
        int r1 = wm + lq + 8;  if (r1 > 48) r1 = 48;
        const float* Q0 = g_QKV + base + (size_t)r0 * 1152;
        const float* Q1 = g_QKV + base + (size_t)r1 * 1152;
        #pragma unroll
        for (int kt = 0; kt < 12; ++kt) {
            int c0 = kt * 8 + lr4;
            qf[kt][0] = __float_as_uint(Q0[c0]);
            qf[kt][1] = __float_as_uint(Q1[c0]);
            qf[kt][2] = __float_as_uint(Q0[c0 + 4]);
            qf[kt][3] = __float_as_uint(Q1[c0 + 4]);
        }
    }
    __syncthreads();

    float acc[7][4];
    #pragma unroll
    for (int nt = 0; nt < 7; ++nt)
        #pragma unroll
        for (int c = 0; c < 4; ++c) acc[nt][c] = 0.f;
    #pragma unroll
    for (int kt = 0; kt < 12; ++kt) {
        #pragma unroll
        for (int nt = 0; nt < 7; ++nt) {
            uint32_t bf[2];
            int nrow = nt * 8 + lq;
            bf[0] = __float_as_uint(KsP[nrow * 100 + kt * 8 + lr4]);
            bf[1] = __float_as_uint(KsP[nrow * 100 + kt * 8 + lr4 + 4]);
            mma_tf32(acc[nt], qf[kt], bf);
        }
    }
    __syncthreads();

    const float scale = 0.10206207261596577f;
    #pragma unroll
    for (int h2 = 0; h2 < 2; ++h2) {
        int i = wm + lq + 8 * h2;
        bool rvalid = i < 49;
        int yi = i / 7, xi = i - yi * 7;
        int gyi = wr * 7 + yi, gxi = wc * 7 + xi;
        int li = ((gyi < 56) ? 0 : ((gyi < 60) ? 1 : 2)) * 3 +
                 ((gxi < 56) ? 0 : ((gxi < 60) ? 1 : 2));
        float pv[14];
        float m = -1e30f;
        #pragma unroll
        for (int nt = 0; nt < 7; ++nt)
            #pragma unroll
            for (int c = 0; c < 2; ++c) {
                int j = nt * 8 + 2 * lr4 + c;
                float v;
                if (j < 49 && rvalid) {
                    int yj = j / 7, xj = j - yj * 7;
                    float bias = rpb[((yi - yj + 6) * 13 + (xi - xj + 6)) * 4 + h];
                    int gyj = wr * 7 + yj, gxj = wc * 7 + xj;
                    int lj = ((gyj < 56) ? 0 : ((gyj < 60) ? 1 : 2)) * 3 +
                             ((gxj < 56) ? 0 : ((gxj < 60) ? 1 : 2));
                    v = acc[nt][h2 * 2 + c] * scale + bias + ((li != lj) ? -100.f : 0.f);
                } else {
                    v = (j < 49) ? 0.f : -1e30f;
                }
                pv[nt * 2 + c] = v;
                m = fmaxf(m, v);
            }
        m = fmaxf(m, __shfl_xor_sync(0xffffffffu, m, 1));
        m = fmaxf(m, __shfl_xor_sync(0xffffffffu, m, 2));
        float s = 0.f;
        #pragma unroll
        for (int t = 0; t < 14; ++t) {
            float e = (pv[t] > -1e29f) ? __expf(pv[t] - m) : 0.f;
            pv[t] = e; s += e;
        }
        s += __shfl_xor_sync(0xffffffffu, s, 1);
        s += __shfl_xor_sync(0xffffffffu, s, 2);
        float inv = 1.f / s;
        #pragma unroll
        for (int nt = 0; nt < 7; ++nt)
            #pragma unroll
            for (int c = 0; c < 2; ++c)
                KsP[i * 60 + nt * 8 + 2 * lr4 + c] = pv[nt * 2 + c] * inv;
    }
    __syncthreads();

    float oacc[12][4];
    #pragma unroll
    for (int dt = 0; dt < 12; ++dt)
        #pragma unroll
        for (int c = 0; c < 4; ++c) oacc[dt][c] = 0.f;
    #pragma unroll
    for (int kt = 0; kt < 7; ++kt) {
        uint32_t af[4];
        int r0 = wm + lq, c0 = kt * 8 + lr4;
        af[0] = __float_as_uint(KsP[r0 * 60 + c0]);
        af[1] = __float_as_uint(KsP[(r0 + 8) * 60 + c0]);
        af[2] = __float_as_uint(KsP[r0 * 60 + c0 + 4]);
        af[3] = __float_as_uint(KsP[(r0 + 8) * 60 + c0 + 4]);
        #pragma unroll
        for (int dt = 0; dt < 12; ++dt) {
            uint32_t bf[2];
            int drow = dt * 8 + lq;
            bf[0] = __float_as_uint(Vt[drow * 61 + c0]);
            bf[1] = __float_as_uint(Vt[drow * 61 + c0 + 4]);
            mma_tf32(oacc[dt], af, bf);
        }
    }

    #pragma unroll
    for (int h2 = 0; h2 < 2; ++h2) {
        int i = wm + lq + 8 * h2;
        if (i >= 49) continue;
        size_t ro = ((size_t)win * 49 + i) * 384 + h * 96;
        #pragma unroll
        for (int dt = 0; dt < 12; ++dt) {
            int d = dt * 8 + 2 * lr4;
            *(float2*)&g_Aout[ro + d] =
                make_float2(oacc[dt][h2 * 2], oacc[dt][h2 * 2 + 1]);
        }
    }
}

// ---------------------------------------------------------------------------
// cp.async helpers
// ---------------------------------------------------------------------------
__device__ __forceinline__ void cpasync16(void* dst, const void* src, bool pred) {
    uint32_t d = (uint32_t)__cvta_generic_to_shared(dst);
    int sz = pred ? 16 : 0;
    asm volatile("cp.async.cg.shared.global [%0], [%1], 16, %2;"
                 :: "r"(d), "l"(src), "r"(sz));
}
__device__ __forceinline__ void cp_commit() {
    asm volatile("cp.async.commit_group;");
}
template<int NN>
__device__ __forceinline__ void cp_wait() {
    asm volatile("cp.async.wait_group %0;" :: "n"(NN));
}

// ---------------------------------------------------------------------------
// TF32 GEMM (R13 champion mainloop): BK=16, 4-stage cp.async, ldmatrix.x4
// fragments, 128 x (NTW*16) CTA tile, 256 threads, warp tile 32 x (NTW*8),
// smem stride 20. NTW=8 for the matmuls (N multiple of 128); NTW=6 for the
// conv (N=192 -> grid.x=2 covers exactly 192 cols, no dead MMAs).
// MODE: 0 plain, 2 +extra, 3 window-reverse scatter (+shortcut),
//       4 implicit-GEMM conv gather + NCHW store + x residual,
//       5 fused LN->fc1->gelu: v = gelu(rs*(acc - mu*bias[n]) + extra[n])
// ---------------------------------------------------------------------------
constexpr int GST   = 4;                          // pipeline stages
constexpr int GSTG  = 128 * 20 * 4;               // bytes per stage per operand
constexpr int GSMEM = GST * 2 * GSTG;             // 81920 bytes

template<int MODE, int NTW>
__global__ __launch_bounds__(256, 2)
void gemm_tc(const float* __restrict__ A, const float* __restrict__ W,
             const float* __restrict__ bias, float* __restrict__ C,
             const float* __restrict__ extra, int M, int N, int K,
             const float* __restrict__ stats)
{
    constexpr int ST = GST;
    extern __shared__ __align__(16) uint32_t dyn[];
    uint32_t* As = dyn;                       // ST stages of 128*20
    uint32_t* Bs = dyn + ST * 128 * 20;       // ST stages of 128*20
    const uint32_t smem0 = (uint32_t)__cvta_generic_to_shared(dyn);

    const int tid  = threadIdx.x;
    const int lane = tid & 31, warp = tid >> 5;
    const int wm = (warp >> 1) * 32, wn = (warp & 1) * (NTW * 8);
    const int m0 = blockIdx.y << 7, n0 = blockIdx.x * (NTW * 16);
    const int lr = tid >> 2;
    const int lc = (tid & 3) * 4;

    // per-thread ldmatrix byte offsets (within one operand stage)
    uint32_t aoff[2], boff[NTW / 2];
    #pragma unroll
    for (int mt = 0; mt < 2; ++mt)
        aoff[mt] = (uint32_t)(((wm + mt * 16 + (lane & 15)) * 20 +
                               ((lane >> 4) << 2)) * 4);
    #pragma unroll
    for (int p = 0; p < NTW / 2; ++p)
        boff[p] = (uint32_t)(((wn + p * 16 + ((lane >> 4) << 3) + (lane & 7)) * 20 +
                              (((lane >> 3) & 1) << 2)) * 4);

    float acc[2][NTW][4];
    #pragma unroll
    for (int a = 0; a < 2; ++a)
        #pragma unroll
        for (int b = 0; b < NTW; ++b)
            #pragma unroll
            for (int c = 0; c < 4; ++c) acc[a][b][c] = 0.f;

    int cb[2], crr[2], ccc[2];
    if (MODE == 4) {
        #pragma unroll
        for (int it = 0; it < 2; ++it) {
            int m = m0 + lr + 64 * it; if (m >= M) m = 0;
            cb[it] = m / 3600; int pix = m - cb[it] * 3600;
            crr[it] = pix / 60; ccc[it] = pix - crr[it] * 60;
        }
    }

    const int KT = K >> 4;

    auto LOADA = [&](int kt, int buf) {
        int k0 = kt * 16;
        uint32_t* as = As + buf * 128 * 20;
        uint32_t* bs = Bs + buf * 128 * 20;
        int tap = 0, ci = 0, dr = 0, dc = 0;
        if (MODE == 4) {
            int k = k0 + lc;
            tap = k / 384; ci = k - tap * 384;
            dr = tap / 3 - 1; dc = (tap % 3) - 1;
        }
        #pragma unroll
        for (int it = 0; it < 2; ++it) {
            int m = m0 + lr + 64 * it;
            const float* asrc = A;
            bool ap = false;
            if (MODE == 4) {
                int rr = crr[it] + dr, cc = ccc[it] + dc;
                ap = (m < M) && (rr >= 0) && (rr < 60) && (cc >= 0) && (cc < 60);
                if (ap) asrc = A + ((size_t)(cb[it] * 63 + rr) * 63 + cc) * 384 + ci;
            } else {
                ap = (m < M);
                if (ap) asrc = A + (size_t)m * K + k0 + lc;
            }
            cpasync16(&as[(lr + 64 * it) * 20 + lc], asrc, ap);
            int n = n0 + lr + 64 * it;
            const float* bsrc = (n < N) ? (W + (size_t)n * K + k0 + lc) : W;
            cpasync16(&bs[(lr + 64 * it) * 20 + lc], bsrc, n < N);
        }
    };

    auto COMPUTE = [&](int buf) {
        const uint32_t abase = smem0 + buf * GSTG;
        const uint32_t bbase = smem0 + (ST + buf) * GSTG;
        #pragma unroll
        for (int ks = 0; ks < 16; ks += 8) {
            uint32_t af[2][4], bf[NTW][2];
            #pragma unroll
            for (int mt = 0; mt < 2; ++mt)
                ldsm_x4(af[mt], abase + aoff[mt] + ks * 4);
            #pragma unroll
            for (int p = 0; p < NTW / 2; ++p) {
                uint32_t d[4];
                ldsm_x4(d, bbase + boff[p] + ks * 4);
                bf[2 * p][0]     = d[0];
                bf[2 * p][1]     = d[1];
                bf[2 * p + 1][0] = d[2];
                bf[2 * p + 1][1] = d[3];
            }
            #pragma unroll
            for (int mt = 0; mt < 2; ++mt)
                #pragma unroll
                for (int nt = 0; nt < NTW; ++nt)
                    mma_tf32(acc[mt][nt], af[mt], bf[nt]);
        }
    };

    #pragma unroll
    for (int s = 0; s < ST - 1; ++s) {
        if (s < KT) LOADA(s, s);
        cp_commit();
    }
    for (int kt = 0; kt < KT; ++kt) {
        cp_wait<ST - 2>();
        __syncthreads();
        COMPUTE(kt % ST);
        int nx = kt + ST - 1;
        if (nx < KT) LOADA(nx, nx % ST);
        cp_commit();
    }

    // ---- epilogue ----
    #pragma unroll
    for (int mt = 0; mt < 2; ++mt) {
        #pragma unroll
        for (int half = 0; half < 2; ++half) {
            int m = m0 + wm + mt * 16 + (lane >> 2) + half * 8;
            if (m >= M) continue;
            size_t rowoff = 0;
            if (MODE == 0 || MODE == 2 || MODE == 5) {
                rowoff = (size_t)m * N;
            } else if (MODE == 3) {
                int b = m / 3969;
                int rem = m - b * 3969;
                int widx = rem / 49, tok = rem - widx * 49;
                int rr = (widx / 9) * 7 + tok / 7;
                int cc = (widx % 9) * 7 + tok % 7;
                int r2 = rr + 3; if (r2 >= 63) r2 -= 63;
                int c2 = cc + 3; if (c2 >= 63) c2 -= 63;
                rowoff = (size_t)((b * 63 + r2) * 63 + c2) * 384;
            }
            int ob = 0, orr = 0, occ = 0;
            if (MODE == 4) {
                ob = m / 3600; int pix = m - ob * 3600;
                orr = pix / 60; occ = pix - orr * 60;
            }
            float mu = 0.f, rs = 0.f;
            if (MODE == 5) { mu = stats[2 * m]; rs = stats[2 * m + 1]; }
            #pragma unroll
            for (int nt = 0; nt < NTW; ++nt) {
                int n = n0 + wn + nt * 8 + 2 * (lane & 3);
                if (n >= N) continue;
                if (MODE == 5) {
                    float v0 = rs * (acc[mt][nt][half * 2]     - mu * bias[n])     + extra[n];
                    float v1 = rs * (acc[mt][nt][half * 2 + 1] - mu * bias[n + 1]) + extra[n + 1];
                    v0 = 0.5f * v0 * (1.f + erff(v0 * 0.70710678118654752f));
                    v1 = 0.5f * v1 * (1.f + erff(v1 * 0.70710678118654752f));
                    *(float2*)&C[rowoff + n] = make_float2(v0, v1);
                    continue;
                }
                float v0 = acc[mt][nt][half * 2]     + bias[n];
                float v1 = acc[mt][nt][half * 2 + 1] + bias[n + 1];
                if (MODE == 0) {
                    *(float2*)&C[rowoff + n] = make_float2(v0, v1);
                } else if (MODE == 2 || MODE == 3) {
                    float2 e = *(const float2*)&extra[rowoff + n];
                    *(float2*)&C[rowoff + n] = make_float2(v0 + e.x, v1 + e.y);
                } else {
                    #pragma unroll
                    for (int c = 0; c < 2; ++c) {
                        int nn = n + c;
                        if (nn >= N) continue;
                        float v = (c == 0) ? v0 : v1;
                        size_t o = (((size_t)ob * 192 + nn) * 60 + orr) * 60 + occ;
                        C[o] = v + extra[o];
                    }
                }
            }
        }
    }
}

// ---------------------------------------------------------------------------
extern "C" void kernel_launch(void* const* d_in, const int* in_sizes, int n_in,
                              void* d_out, int out_size)
{
    const float* x      = (const float*)d_in[0];
    const float* g      = (const float*)d_in[1];
    const float* norm_w = (const float*)d_in[2];
    const float* norm_b = (const float*)d_in[3];
    const float* n1_w   = (const float*)d_in[4];
    const float* n1_b   = (const float*)d_in[5];
    const float* qkv_w  = (const float*)d_in[6];
    const float* qkv_b  = (const float*)d_in[7];
    const float* proj_w = (const float*)d_in[8];
    const float* proj_b = (const float*)d_in[9];
    const float* rpb    = (const float*)d_in[10];
    const float* n2_w   = (const float*)d_in[11];
    const float* n2_b   = (const float*)d_in[12];
    const float* fc1_w  = (const float*)d_in[13];
    const float* fc1_b  = (const float*)d_in[14];
    const float* fc2_w  = (const float*)d_in[15];
    const float* fc2_b  = (const float*)d_in[16];
    const float* conv_w = (const float*)d_in[17];
    const float* conv_b = (const float*)d_in[18];
    float* out = (float*)d_out;

    float *pZ, *pWtok, *pQKV, *pAout, *pZ2, *pH, *pZf, *pW2;
    float *pW1p, *pHn, *pCn, *pStat;
    cudaGetSymbolAddress((void**)&pZ,    g_Z);
    cudaGetSymbolAddress((void**)&pWtok, g_Wtok);
    cudaGetSymbolAddress((void**)&pQKV,  g_QKV);
    cudaGetSymbolAddress((void**)&pAout, g_Aout);
    cudaGetSymbolAddress((void**)&pZ2,   g_Z2);
    cudaGetSymbolAddress((void**)&pH,    g_H);
    cudaGetSymbolAddress((void**)&pZf,   g_Zf);
    cudaGetSymbolAddress((void**)&pW2,   g_W2);
    cudaGetSymbolAddress((void**)&pW1p,  g_W1p);
    cudaGetSymbolAddress((void**)&pHn,   g_Hn);
    cudaGetSymbolAddress((void**)&pCn,   g_Cn);
    cudaGetSymbolAddress((void**)&pStat, g_Stat);

    cudaFuncSetAttribute((const void*)gemm_tc<0, 8>, cudaFuncAttributeMaxDynamicSharedMemorySize, GSMEM);
    cudaFuncSetAttribute((const void*)gemm_tc<2, 8>, cudaFuncAttributeMaxDynamicSharedMemorySize, GSMEM);
    cudaFuncSetAttribute((const void*)gemm_tc<3, 8>, cudaFuncAttributeMaxDynamicSharedMemorySize, GSMEM);
    cudaFuncSetAttribute((const void*)gemm_tc<4, 6>, cudaFuncAttributeMaxDynamicSharedMemorySize, GSMEM);
    cudaFuncSetAttribute((const void*)gemm_tc<5, 8>, cudaFuncAttributeMaxDynamicSharedMemorySize, GSMEM);

    const int MT = (kTok + 127) / 128;  // 249

    repack_conv<<<(kDim * kC2 * 9 + 255) / 256, 256>>>(conv_w);
    prep_fc1<<<kMlp, 128>>>(fc1_w, fc1_b, n2_w, n2_b);
    prep_kernel<<<kTok / 4, 128>>>(x, g, norm_w, norm_b, n1_w, n1_b);
    gemm_tc<0, 8><<<dim3(9, MT), 256, GSMEM>>>(pWtok, qkv_w, qkv_b, pQKV, nullptr, kTok, 1152, 384, nullptr);
    attn_mma<<<648 * 4, 128>>>(rpb);
    gemm_tc<3, 8><<<dim3(3, MT), 256, GSMEM>>>(pAout, proj_w, proj_b, pZ2, pZ, kTok, 384, 384, nullptr);
    ln_stats<<<kTok / 4, 128>>>(pZ2);
    gemm_tc<5, 8><<<dim3(12, MT), 256, GSMEM>>>(pZ2, pW1p, pHn, pH, pCn, kTok, 1536, 384, pStat);
    gemm_tc<2, 8><<<dim3(3, MT), 256, GSMEM>>>(pH, fc2_w, fc2_b, pZf, pZ2, kTok, 384, 1536, nullptr);
    gemm_tc<4, 6><<<dim3(2, 225), 256, GSMEM>>>(pZf, pW2, conv_b, out, x, 28800, 192, 3456, nullptr);
}